// round 8
// baseline (speedup 1.0000x reference)
#include <cuda_runtime.h>
#include <cstdint>

// Problem constants
#define NB 4
#define NS 2048
#define ND 1024
#define NH 16
#define NDK 64
#define NM (NB*NS)   // 8192

// Persistent scratch (device globals: allocation-free, graph-safe)
__device__ float g_q[(size_t)NM * ND];    // [B,H,S,dk] (tf32-rounded)
__device__ float g_k[(size_t)NM * ND];    // [B,H,S,dk] (tf32-rounded)
__device__ float g_v[(size_t)NM * ND];    // [B,H,S,dk] (tf32-rounded)
__device__ float g_ctx[(size_t)NM * ND];  // [B,S,D]    (fp32)

// ---------------------------------------------------------------------------
// tf32 helpers
// ---------------------------------------------------------------------------
__device__ __forceinline__ float f2tf(float x) {
    uint32_t u;
    asm("cvt.rna.tf32.f32 %0, %1;" : "=r"(u) : "f"(x));
    return __uint_as_float(u);
}

__device__ __forceinline__ void mma_tf32(float d[4],
                                         uint32_t a0, uint32_t a1,
                                         uint32_t a2, uint32_t a3,
                                         uint32_t b0, uint32_t b1) {
    asm volatile(
        "mma.sync.aligned.m16n8k8.row.col.f32.tf32.tf32.f32 "
        "{%0,%1,%2,%3}, {%4,%5,%6,%7}, {%8,%9}, {%0,%1,%2,%3};"
        : "+f"(d[0]), "+f"(d[1]), "+f"(d[2]), "+f"(d[3])
        : "r"(a0), "r"(a1), "r"(a2), "r"(a3), "r"(b0), "r"(b1));
}

// ---------------------------------------------------------------------------
// GEMM: out[m,n] = sum_k X[m,k]*W[n,k] + bias[n]   (tf32 tensor cores)
// 128x128 tile, BK=16, 256 threads (8 warps: 4 m x 2 n), warp tile 32x64.
// Identical to the Round-4 passing version.
// ---------------------------------------------------------------------------
#define BKG 16

__global__ __launch_bounds__(256, 2)
void gemm_bias_k(const float* __restrict__ Xin, int x_sel,
                 const float* __restrict__ W, const float* __restrict__ bias,
                 float* __restrict__ Oout, int out_sel)
{
    const float* X = (x_sel == 0) ? Xin : g_ctx;
    float* out = (out_sel == 0) ? g_q : (out_sel == 1) ? g_k :
                 (out_sel == 2) ? g_v : Oout;

    __shared__ float As[2][128][20];
    __shared__ float Bs[2][128][20];

    const int tid  = threadIdx.x;
    const int lane = tid & 31;
    const int warp = tid >> 5;
    const int g    = lane >> 2;
    const int tg   = lane & 3;
    const int wm   = warp & 3;
    const int wn   = warp >> 2;
    const int row0 = blockIdx.y * 128;
    const int col0 = blockIdx.x * 128;

    float d[2][8][4];
    #pragma unroll
    for (int mi = 0; mi < 2; mi++)
        #pragma unroll
        for (int ni = 0; ni < 8; ni++)
            #pragma unroll
            for (int q = 0; q < 4; q++) d[mi][ni][q] = 0.f;

    #pragma unroll
    for (int w = 0; w < 2; w++) {
        int f  = tid + w * 256;
        int r  = f >> 2;
        int kb = (f & 3) << 2;
        float4 a = *(const float4*)(X + (size_t)(row0 + r) * ND + kb);
        float4 b = *(const float4*)(W + (size_t)(col0 + r) * ND + kb);
        *(float4*)&As[0][r][kb] = make_float4(f2tf(a.x), f2tf(a.y), f2tf(a.z), f2tf(a.w));
        *(float4*)&Bs[0][r][kb] = make_float4(f2tf(b.x), f2tf(b.y), f2tf(b.z), f2tf(b.w));
    }
    __syncthreads();

    #pragma unroll 2
    for (int k0 = 0; k0 < ND; k0 += BKG) {
        const int buf = (k0 >> 4) & 1;
        const int nxt = buf ^ 1;
        const bool more = (k0 + BKG) < ND;

        float4 pa[2], pb[2];
        if (more) {
            #pragma unroll
            for (int w = 0; w < 2; w++) {
                int f  = tid + w * 256;
                int r  = f >> 2;
                int kb = (f & 3) << 2;
                pa[w] = *(const float4*)(X + (size_t)(row0 + r) * ND + k0 + BKG + kb);
                pb[w] = *(const float4*)(W + (size_t)(col0 + r) * ND + k0 + BKG + kb);
            }
        }

        #pragma unroll
        for (int k8 = 0; k8 < BKG; k8 += 8) {
            uint32_t af[2][4], bf[8][2];
            #pragma unroll
            for (int mi = 0; mi < 2; mi++) {
                int rm = wm * 32 + mi * 16;
                af[mi][0] = __float_as_uint(As[buf][rm + g    ][k8 + tg]);
                af[mi][1] = __float_as_uint(As[buf][rm + g + 8][k8 + tg]);
                af[mi][2] = __float_as_uint(As[buf][rm + g    ][k8 + tg + 4]);
                af[mi][3] = __float_as_uint(As[buf][rm + g + 8][k8 + tg + 4]);
            }
            #pragma unroll
            for (int ni = 0; ni < 8; ni++) {
                int cn = wn * 64 + ni * 8;
                bf[ni][0] = __float_as_uint(Bs[buf][cn + g][k8 + tg]);
                bf[ni][1] = __float_as_uint(Bs[buf][cn + g][k8 + tg + 4]);
            }
            #pragma unroll
            for (int mi = 0; mi < 2; mi++)
                #pragma unroll
                for (int ni = 0; ni < 8; ni++)
                    mma_tf32(d[mi][ni], af[mi][0], af[mi][1], af[mi][2], af[mi][3],
                             bf[ni][0], bf[ni][1]);
        }

        if (more) {
            #pragma unroll
            for (int w = 0; w < 2; w++) {
                int f  = tid + w * 256;
                int r  = f >> 2;
                int kb = (f & 3) << 2;
                *(float4*)&As[nxt][r][kb] =
                    make_float4(f2tf(pa[w].x), f2tf(pa[w].y), f2tf(pa[w].z), f2tf(pa[w].w));
                *(float4*)&Bs[nxt][r][kb] =
                    make_float4(f2tf(pb[w].x), f2tf(pb[w].y), f2tf(pb[w].z), f2tf(pb[w].w));
            }
            __syncthreads();
        }
    }

    #pragma unroll
    for (int mi = 0; mi < 2; mi++) {
        #pragma unroll
        for (int ni = 0; ni < 8; ni++) {
            int c0 = col0 + wn * 64 + ni * 8 + tg * 2;
            float2 bb = *(const float2*)(bias + c0);
            int r0 = row0 + wm * 32 + mi * 16 + g;
            float2 v0 = make_float2(d[mi][ni][0] + bb.x, d[mi][ni][1] + bb.y);
            float2 v1 = make_float2(d[mi][ni][2] + bb.x, d[mi][ni][3] + bb.y);
            if (out_sel <= 2) {
                v0.x = f2tf(v0.x); v0.y = f2tf(v0.y);
                v1.x = f2tf(v1.x); v1.y = f2tf(v1.y);
                int hh = c0 >> 6, d0 = c0 & 63;
                int bt = r0 >> 11, s0 = r0 & (NS - 1);
                *(float2*)(out + (((size_t)(bt * NH + hh) * NS + s0) * NDK + d0)) = v0;
                int r1 = r0 + 8;
                int bt1 = r1 >> 11, s1 = r1 & (NS - 1);
                *(float2*)(out + (((size_t)(bt1 * NH + hh) * NS + s1) * NDK + d0)) = v1;
            } else {
                *(float2*)(out + (size_t)r0 * ND + c0) = v0;
                *(float2*)(out + (size_t)(r0 + 8) * ND + c0) = v1;
            }
        }
    }
}

// ---------------------------------------------------------------------------
// Flash attention (tf32 mma.sync), 128 threads / 4 warps.
// Each warp owns 32 q-rows (2 row-blocks of 16) -> K/V fragments loaded once
// per warp and reused for both row-blocks (halves per-row LDS traffic).
// ---------------------------------------------------------------------------
#define KSOFF (128*68)
#define VSOFF (128*68 + 64*68)
#define ATTN_SMEM ((128*68 + 64*68 + 64*72) * 4)   // 70656 bytes

__global__ __launch_bounds__(128)
void attn_k(const float* __restrict__ relpos)
{
    extern __shared__ float sm[];
    float (*ps)[68] = (float(*)[68])sm;            // [128][68] P tile
    float (*ks)[68] = (float(*)[68])(sm + KSOFF);  // [64][68]  K tile
    float (*vs)[72] = (float(*)[72])(sm + VSOFF);  // [64][72]  V tile

    const int b    = blockIdx.x & (NB - 1);
    const int qt   = blockIdx.x >> 2;
    const int h    = blockIdx.y;
    const int tid  = threadIdx.x;
    const int lane = tid & 31;
    const int warp = tid >> 5;            // 0..3
    const int g    = lane >> 2;
    const int tg   = lane & 3;

    const float* qptr  = g_q + ((size_t)(b*NH + h) * NS + (size_t)qt*128) * NDK;
    const float* kbase = g_k + ((size_t)(b*NH + h) * NS) * NDK;
    const float* vbase = g_v + ((size_t)(b*NH + h) * NS) * NDK;
    const float* bias0 = relpos + ((size_t)h * NS + (size_t)qt*128 + warp*32) * NS;

    // Q fragments: rows warp*32 + g + {0,8} (rb0) and {16,24} (rb1)
    uint32_t qa[8][4], qb[8][4];
    {
        const float* q0 = qptr + (size_t)(warp*32 + g) * NDK;
        #pragma unroll
        for (int k8 = 0; k8 < 8; k8++) {
            qa[k8][0] = __float_as_uint(q0[k8*8 + tg]);
            qa[k8][1] = __float_as_uint(q0[8*NDK  + k8*8 + tg]);
            qa[k8][2] = __float_as_uint(q0[k8*8 + tg + 4]);
            qa[k8][3] = __float_as_uint(q0[8*NDK  + k8*8 + tg + 4]);
            qb[k8][0] = __float_as_uint(q0[16*NDK + k8*8 + tg]);
            qb[k8][1] = __float_as_uint(q0[24*NDK + k8*8 + tg]);
            qb[k8][2] = __float_as_uint(q0[16*NDK + k8*8 + tg + 4]);
            qb[k8][3] = __float_as_uint(q0[24*NDK + k8*8 + tg + 4]);
        }
    }

    float o[2][8][4];
    #pragma unroll
    for (int rb = 0; rb < 2; rb++)
        #pragma unroll
        for (int ni = 0; ni < 8; ni++)
            #pragma unroll
            for (int q = 0; q < 4; q++) o[rb][ni][q] = 0.f;
    float mrow[2][2] = {{-1e30f, -1e30f}, {-1e30f, -1e30f}};
    float lrow[2][2] = {{0.f, 0.f}, {0.f, 0.f}};

    for (int kt = 0; kt < NS/64; kt++) {
        __syncthreads();   // prior iteration's reads of ks/vs complete
        #pragma unroll
        for (int w = 0; w < 8; w++) {
            int f  = tid + w*128;          // 0..1023
            int r  = f >> 4;               // 0..63
            int dd = (f & 15) << 2;        // 0..60
            *(float4*)&ks[r][dd] = *(const float4*)(kbase + (size_t)(kt*64 + r)*NDK + dd);
            *(float4*)&vs[r][dd] = *(const float4*)(vbase + (size_t)(kt*64 + r)*NDK + dd);
        }
        __syncthreads();

        // GEMM1: both row-blocks share each K fragment
        float s[2][8][4];
        #pragma unroll
        for (int rb = 0; rb < 2; rb++)
            #pragma unroll
            for (int ni = 0; ni < 8; ni++)
                #pragma unroll
                for (int q = 0; q < 4; q++) s[rb][ni][q] = 0.f;

        #pragma unroll
        for (int k8 = 0; k8 < 8; k8++) {
            uint32_t bf[8][2];
            #pragma unroll
            for (int ni = 0; ni < 8; ni++) {
                bf[ni][0] = __float_as_uint(ks[ni*8 + g][k8*8 + tg]);
                bf[ni][1] = __float_as_uint(ks[ni*8 + g][k8*8 + tg + 4]);
            }
            #pragma unroll
            for (int ni = 0; ni < 8; ni++) {
                mma_tf32(s[0][ni], qa[k8][0], qa[k8][1], qa[k8][2], qa[k8][3],
                         bf[ni][0], bf[ni][1]);
                mma_tf32(s[1][ni], qb[k8][0], qb[k8][1], qb[k8][2], qb[k8][3],
                         bf[ni][0], bf[ni][1]);
            }
        }

        // Softmax per row-block (rows g, g+8 within block; quad shfl reduce)
        #pragma unroll
        for (int rb = 0; rb < 2; rb++) {
            float2 br0[8], br1[8];
            const float* bp0 = bias0 + (size_t)(rb*16 + g) * NS + kt*64 + tg*2;
            const float* bp1 = bp0 + 8 * NS;
            #pragma unroll
            for (int ni = 0; ni < 8; ni++) {
                br0[ni] = *(const float2*)(bp0 + ni*8);
                br1[ni] = *(const float2*)(bp1 + ni*8);
            }

            float nm0 = mrow[rb][0], nm1 = mrow[rb][1];
            #pragma unroll
            for (int ni = 0; ni < 8; ni++) {
                s[rb][ni][0] = fmaf(s[rb][ni][0], 0.125f, br0[ni].x);
                s[rb][ni][1] = fmaf(s[rb][ni][1], 0.125f, br0[ni].y);
                s[rb][ni][2] = fmaf(s[rb][ni][2], 0.125f, br1[ni].x);
                s[rb][ni][3] = fmaf(s[rb][ni][3], 0.125f, br1[ni].y);
                nm0 = fmaxf(nm0, fmaxf(s[rb][ni][0], s[rb][ni][1]));
                nm1 = fmaxf(nm1, fmaxf(s[rb][ni][2], s[rb][ni][3]));
            }
            nm0 = fmaxf(nm0, __shfl_xor_sync(0xffffffffu, nm0, 1));
            nm0 = fmaxf(nm0, __shfl_xor_sync(0xffffffffu, nm0, 2));
            nm1 = fmaxf(nm1, __shfl_xor_sync(0xffffffffu, nm1, 1));
            nm1 = fmaxf(nm1, __shfl_xor_sync(0xffffffffu, nm1, 2));

            float corr0 = __expf(mrow[rb][0] - nm0);
            float corr1 = __expf(mrow[rb][1] - nm1);
            float rs0 = 0.f, rs1 = 0.f;
            const int pr = warp*32 + rb*16 + g;
            #pragma unroll
            for (int ni = 0; ni < 8; ni++) {
                s[rb][ni][0] = __expf(s[rb][ni][0] - nm0);
                s[rb][ni][1] = __expf(s[rb][ni][1] - nm0);
                s[rb][ni][2] = __expf(s[rb][ni][2] - nm1);
                s[rb][ni][3] = __expf(s[rb][ni][3] - nm1);
                rs0 += s[rb][ni][0] + s[rb][ni][1];
                rs1 += s[rb][ni][2] + s[rb][ni][3];
                int c = ni*8 + tg*2;
                *(float2*)&ps[pr    ][c] = make_float2(f2tf(s[rb][ni][0]), f2tf(s[rb][ni][1]));
                *(float2*)&ps[pr + 8][c] = make_float2(f2tf(s[rb][ni][2]), f2tf(s[rb][ni][3]));
            }
            rs0 += __shfl_xor_sync(0xffffffffu, rs0, 1);
            rs0 += __shfl_xor_sync(0xffffffffu, rs0, 2);
            rs1 += __shfl_xor_sync(0xffffffffu, rs1, 1);
            rs1 += __shfl_xor_sync(0xffffffffu, rs1, 2);
            lrow[rb][0] = lrow[rb][0] * corr0 + rs0;
            lrow[rb][1] = lrow[rb][1] * corr1 + rs1;
            mrow[rb][0] = nm0; mrow[rb][1] = nm1;
            #pragma unroll
            for (int ni = 0; ni < 8; ni++) {
                o[rb][ni][0] *= corr0; o[rb][ni][1] *= corr0;
                o[rb][ni][2] *= corr1; o[rb][ni][3] *= corr1;
            }
        }
        __syncwarp();   // order ps stores before intra-warp frag reloads

        // GEMM2: both row-blocks share each V fragment
        #pragma unroll
        for (int k8 = 0; k8 < 8; k8++) {
            uint32_t af0[4], af1[4];
            const int pr = warp*32 + g;
            af0[0] = __float_as_uint(ps[pr     ][k8*8 + tg]);
            af0[1] = __float_as_uint(ps[pr +  8][k8*8 + tg]);
            af0[2] = __float_as_uint(ps[pr     ][k8*8 + tg + 4]);
            af0[3] = __float_as_uint(ps[pr +  8][k8*8 + tg + 4]);
            af1[0] = __float_as_uint(ps[pr + 16][k8*8 + tg]);
            af1[1] = __float_as_uint(ps[pr + 24][k8*8 + tg]);
            af1[2] = __float_as_uint(ps[pr + 16][k8*8 + tg + 4]);
            af1[3] = __float_as_uint(ps[pr + 24][k8*8 + tg + 4]);
            uint32_t bf[8][2];
            #pragma unroll
            for (int ni = 0; ni < 8; ni++) {
                bf[ni][0] = __float_as_uint(vs[k8*8 + tg    ][ni*8 + g]);
                bf[ni][1] = __float_as_uint(vs[k8*8 + tg + 4][ni*8 + g]);
            }
            #pragma unroll
            for (int ni = 0; ni < 8; ni++) {
                mma_tf32(o[0][ni], af0[0], af0[1], af0[2], af0[3], bf[ni][0], bf[ni][1]);
                mma_tf32(o[1][ni], af1[0], af1[1], af1[2], af1[3], bf[ni][0], bf[ni][1]);
            }
        }
    }

    // Normalize and write O to g_ctx [B,S,D]
    #pragma unroll
    for (int rb = 0; rb < 2; rb++) {
        float inv0 = 1.f / lrow[rb][0], inv1 = 1.f / lrow[rb][1];
        int r0 = qt*128 + warp*32 + rb*16 + g;
        #pragma unroll
        for (int ni = 0; ni < 8; ni++) {
            int c = h*64 + ni*8 + tg*2;
            *(float2*)(g_ctx + (size_t)(b*NS + r0    ) * ND + c) =
                make_float2(o[rb][ni][0]*inv0, o[rb][ni][1]*inv0);
            *(float2*)(g_ctx + (size_t)(b*NS + r0 + 8) * ND + c) =
                make_float2(o[rb][ni][2]*inv1, o[rb][ni][3]*inv1);
        }
    }
}

// ---------------------------------------------------------------------------
extern "C" void kernel_launch(void* const* d_in, const int* in_sizes, int n_in,
                              void* d_out, int out_size)
{
    const float* Q      = (const float*)d_in[0];
    const float* K      = (const float*)d_in[1];
    const float* V      = (const float*)d_in[2];
    const float* Wq     = (const float*)d_in[3];
    const float* bq     = (const float*)d_in[4];
    const float* Wk     = (const float*)d_in[5];
    const float* bk     = (const float*)d_in[6];
    const float* Wv     = (const float*)d_in[7];
    const float* bv     = (const float*)d_in[8];
    const float* Wo     = (const float*)d_in[9];
    const float* bo     = (const float*)d_in[10];
    const float* relpos = (const float*)d_in[11];
    float* out = (float*)d_out;

    cudaFuncSetAttribute(attn_k, cudaFuncAttributeMaxDynamicSharedMemorySize,
                         ATTN_SMEM);

    dim3 gproj(ND/128, NM/128);   // (8, 64)

    gemm_bias_k<<<gproj, 256>>>(Q, 0, Wq, bq, nullptr, 0);
    gemm_bias_k<<<gproj, 256>>>(K, 0, Wk, bk, nullptr, 1);
    gemm_bias_k<<<gproj, 256>>>(V, 0, Wv, bv, nullptr, 2);

    dim3 gattn(NB * (NS/128), NH);  // (64, 16), batch fastest for L2 bias reuse
    attn_k<<<gattn, 128, ATTN_SMEM>>>(relpos);

    gemm_bias_k<<<gproj, 256>>>(nullptr, 1, Wo, bo, out, 3);
}